// round 10
// baseline (speedup 1.0000x reference)
#include <cuda_runtime.h>

#define D_COLS   4096
#define K_SEL    2048
#define NTHREADS 128
#define VPT      32               // D_COLS / NTHREADS
#define NWARP    (NTHREADS / 32)  // 4
#define CAND_MAX 128

#define F_PINF  __int_as_float(0x7f800000)
#define F_NINF  __int_as_float(0xff800000)
#define DENS0     1634.07f        // 4096 * phi(0)
#define INV_DENS0 6.119698e-4f    // 1 / DENS0
#define MARGIN_B  25.0f           // probe B overshoot (targets count K -/+ MARGIN_B)
#define MARGIN_C  48.5f

// Monotone float <-> ordered-uint key mapping (total order matching float <)
__device__ __forceinline__ unsigned fkey(float f) {
    unsigned u = __float_as_uint(f);
    return u ^ ((u & 0x80000000u) ? 0xFFFFFFFFu : 0x80000000u);
}
__device__ __forceinline__ float funkey(unsigned k) {
    unsigned u = k ^ ((k & 0x80000000u) ? 0x80000000u : 0xFFFFFFFFu);
    return __uint_as_float(u);
}
__device__ __forceinline__ bool my_finite(float f) { return fabsf(f) < 3.0e38f; }

// block count of (v >= T): predicated FADD accumulators (fma pipe), REDUX, LDS.128 bcast
__device__ __forceinline__ int block_count(const float* v, float T,
                                           int4* s_slot, int lane, int wid)
{
    float cf0 = 0.f, cf1 = 0.f, cf2 = 0.f, cf3 = 0.f;
    #pragma unroll
    for (int i = 0; i < VPT; i += 4) {
        if (v[i+0] >= T) cf0 += 1.f;
        if (v[i+1] >= T) cf1 += 1.f;
        if (v[i+2] >= T) cf2 += 1.f;
        if (v[i+3] >= T) cf3 += 1.f;
    }
    int cc = (int)((cf0 + cf1) + (cf2 + cf3));
    cc = __reduce_add_sync(0xffffffffu, cc);
    if (lane == 0) ((int*)s_slot)[wid] = cc;
    __syncthreads();
    int4 p = *s_slot;
    return (p.x + p.y) + (p.z + p.w);
}

__global__ __launch_bounds__(NTHREADS, 8) void sparsify1d_kernel(
    const float* __restrict__ x, float* __restrict__ out)
{
    __shared__ __align__(16) int4  s_redi[2];
    __shared__ __align__(16) float s_redf[NWARP];
    __shared__ float s_thresh;
    __shared__ float s_csum;
    __shared__ int   s_ncand;
    __shared__ float s_cand[CAND_MAX];

    const int t    = threadIdx.x;
    const int lane = t & 31;
    const int wid  = t >> 5;
    const long long row = blockIdx.x;

    const float4* __restrict__ xr   = (const float4*)(x + row * (long long)D_COLS);
    float4* __restrict__       orow = (float4*)(out + row * (long long)D_COLS);

    if (t == 0) s_ncand = 0;      // published by probe A's barrier

    // ---- load row into registers; FUSED probe A (count v >= 0) in load shadow ----
    float v[VPT];
    float ca0 = 0.f, ca1 = 0.f, ca2 = 0.f, ca3 = 0.f;
    #pragma unroll
    for (int i = 0; i < 8; i++) {
        float4 f4 = xr[t + i * NTHREADS];
        v[4*i+0] = f4.x; v[4*i+1] = f4.y; v[4*i+2] = f4.z; v[4*i+3] = f4.w;
        if (f4.x >= 0.f) ca0 += 1.f;
        if (f4.y >= 0.f) ca1 += 1.f;
        if (f4.z >= 0.f) ca2 += 1.f;
        if (f4.w >= 0.f) ca3 += 1.f;
    }
    int cA = (int)((ca0 + ca1) + (ca2 + ca3));
    cA = __reduce_add_sync(0xffffffffu, cA);
    if (lane == 0) ((int*)&s_redi[0])[wid] = cA;
    __syncthreads();
    {
        int4 p = s_redi[0];
        cA = (p.x + p.y) + (p.z + p.w);
    }

    // ---- probe B: overshooting Newton step (targets count K -/+ MARGIN_B) ----
    // If cA >= K, thresh >= 0: aim past it (count K - MARGIN_B) so cB < K w.h.p.
    // If cA <  K, thresh <  0: aim at count K + MARGIN_B so cB >= K w.h.p.
    float dA = (float)(cA - K_SEL);
    float T1 = ((dA >= 0.f) ? (dA + MARGIN_B) : (dA - MARGIN_B)) * INV_DENS0;
    int   cB = block_count(v, T1, &s_redi[1], lane, wid);

    // ---- build bracket: count(>=lo)=clo >= K > chi=count(>=hi) ----
    float lo = F_NINF, hi = F_PINF;
    int clo = D_COLS, chi = 0;
    if (cA >= K_SEL) { lo = 0.0f; clo = cA; } else { hi = 0.0f; chi = cA; }
    if (T1 > lo && T1 < hi) {
        if (cB >= K_SEL) { lo = T1; clo = cB; } else { hi = T1; chi = cB; }
    }

    // ---- probe C (rare): margin-targeted from nearer end ----
    if (clo - chi > CAND_MAX) {
        float d_lo = (float)(clo - K_SEL);
        float d_hi = (float)(K_SEL - chi);
        bool fromLo = d_lo <= d_hi;
        float e  = fromLo ? lo : hi;
        float dd = fromLo ? d_lo : d_hi;
        float inv_dens = __expf(0.5f * e * e) * INV_DENS0;
        float step = (dd + MARGIN_C) * inv_dens;
        float T2 = fromLo ? (lo + step) : (hi - step);
        if (T2 > lo && T2 < hi) {
            int c2 = block_count(v, T2, &s_redi[0], lane, wid);
            if (c2 >= K_SEL) { lo = T2; clo = c2; }
            else             { hi = T2; chi = c2; }
        }
    }

    float thresh = 0.f;
    bool  have_thresh = false;
    int   par = 1;

    // ---- fallback refinement loop (very rare) ----
    for (int iter = 0; iter < 48; iter++) {
        int m = clo - chi;
        if (m <= CAND_MAX) break;

        unsigned klo = fkey(lo), khi = fkey(hi);
        if (khi - klo <= 1u) { thresh = lo; have_thresh = true; break; }

        bool lof = my_finite(lo), hif = my_finite(hi);
        float stepl = (float)(clo - K_SEL) + 0.5f;
        float steph = (float)(K_SEL - chi) + 0.5f;
        float Ti = lo + (hi - lo) * (stepl / (float)m);
        float Tl = lo + stepl / (DENS0 * __expf(-0.5f * lo * lo));
        float Th = hi - steph / (DENS0 * __expf(-0.5f * hi * hi));
        float T  = (lof && hif) ? Ti : (lof ? Tl : Th);
        bool ok  = (T > lo) && (T < hi) && (iter < 12);
        if (!ok) T = funkey(klo + ((khi - klo) >> 1u));   // guaranteed progress

        int cc = block_count(v, T, &s_redi[par], lane, wid);
        par ^= 1;
        if (cc >= K_SEL) { lo = T; clo = cc; }
        else             { hi = T; chi = cc; }
    }

    float total;
    if (!have_thresh) {
        // ---- single sweep: predicated sum of v>=hi + warp-guarded gather ----
        float ssel = 0.f;
        #pragma unroll
        for (int i = 0; i < VPT; i++) {
            float f = v[i];
            if (f >= hi) ssel += f;
            bool inr = (f >= lo) && (f < hi);
            if (__any_sync(0xffffffffu, inr)) {     // warp-uniform skip
                if (inr) {
                    int idx = atomicAdd(&s_ncand, 1);
                    if (idx < CAND_MAX) s_cand[idx] = f;
                }
            }
        }
        ssel += __shfl_xor_sync(0xffffffffu, ssel, 16);
        ssel += __shfl_xor_sync(0xffffffffu, ssel, 8);
        ssel += __shfl_xor_sync(0xffffffffu, ssel, 4);
        ssel += __shfl_xor_sync(0xffffffffu, ssel, 2);
        ssel += __shfl_xor_sync(0xffffffffu, ssel, 1);
        if (lane == 0) s_redf[wid] = ssel;
        __syncthreads();
        float4 pf = *(const float4*)s_redf;
        float ssel_total = (pf.x + pf.y) + (pf.z + pf.w);

        // ---- warp 0: 128-element bitonic sort (4 vals/lane), pick j-th largest ----
        if (wid == 0) {
            int m2 = s_ncand;             // == clo - chi  (<= 128)
            int j  = K_SEL - chi;         // 1-indexed descending rank, 1 <= j <= m2
            float a[4];
            #pragma unroll
            for (int r = 0; r < 4; r++)
                a[r] = (lane + 32*r < m2) ? s_cand[lane + 32*r] : F_NINF;
            #pragma unroll
            for (int k = 2; k <= 128; k <<= 1) {
                #pragma unroll
                for (int j2 = k >> 1; j2 > 0; j2 >>= 1) {
                    if (j2 >= 32) {
                        int jr = j2 >> 5;          // 1 or 2
                        #pragma unroll
                        for (int r = 0; r < 4; r++) {
                            if ((r & jr) == 0) {
                                int rp = r | jr;
                                int e = r * 32 + lane;
                                bool up = ((e & k) == 0);
                                float mn = fminf(a[r], a[rp]);
                                float mx = fmaxf(a[r], a[rp]);
                                a[r]  = up ? mn : mx;
                                a[rp] = up ? mx : mn;
                            }
                        }
                    } else {
                        #pragma unroll
                        for (int r = 0; r < 4; r++) {
                            float b = __shfl_xor_sync(0xffffffffu, a[r], j2);
                            int e = r * 32 + lane;
                            bool up    = ((e & k) == 0);
                            bool lower = ((lane & j2) == 0);
                            float mn = fminf(a[r], b), mx = fmaxf(a[r], b);
                            a[r] = (up == lower) ? mn : mx;
                        }
                    }
                }
            }
            // ascending over e = r*32+lane; j-th largest sits at g = 128 - j
            int g = 128 - j;
            int gl = g & 31;
            float t0 = __shfl_sync(0xffffffffu, a[0], gl);
            float t1 = __shfl_sync(0xffffffffu, a[1], gl);
            float t2 = __shfl_sync(0xffffffffu, a[2], gl);
            float t3 = __shfl_sync(0xffffffffu, a[3], gl);
            int gr = g >> 5;
            float th = (gr == 0) ? t0 : (gr == 1) ? t1 : (gr == 2) ? t2 : t3;
            float cs = 0.f;
            #pragma unroll
            for (int r = 0; r < 4; r++) if (a[r] >= th) cs += a[r];
            cs += __shfl_xor_sync(0xffffffffu, cs, 16);
            cs += __shfl_xor_sync(0xffffffffu, cs, 8);
            cs += __shfl_xor_sync(0xffffffffu, cs, 4);
            cs += __shfl_xor_sync(0xffffffffu, cs, 2);
            cs += __shfl_xor_sync(0xffffffffu, cs, 1);
            if (lane == 0) { s_thresh = th; s_csum = cs; }
        }
        __syncthreads();
        thresh = s_thresh;
        total  = ssel_total + s_csum;
    } else {
        // ---- rare path: thresh known exactly; plain masked sum ----
        float ss = 0.f;
        #pragma unroll
        for (int i = 0; i < VPT; i++) if (v[i] >= thresh) ss += v[i];
        ss += __shfl_xor_sync(0xffffffffu, ss, 16);
        ss += __shfl_xor_sync(0xffffffffu, ss, 8);
        ss += __shfl_xor_sync(0xffffffffu, ss, 4);
        ss += __shfl_xor_sync(0xffffffffu, ss, 2);
        ss += __shfl_xor_sync(0xffffffffu, ss, 1);
        if (lane == 0) s_redf[wid] = ss;
        __syncthreads();
        float4 pf = *(const float4*)s_redf;
        total = (pf.x + pf.y) + (pf.z + pf.w);
    }

    float scale = (float)D_COLS / total;   // out = res * D / sum(res)

    // ---- final predicated scale + coalesced store ----
    #pragma unroll
    for (int i = 0; i < 8; i++) {
        float4 o;
        o.x = (v[4*i+0] >= thresh) ? v[4*i+0] * scale : 0.f;
        o.y = (v[4*i+1] >= thresh) ? v[4*i+1] * scale : 0.f;
        o.z = (v[4*i+2] >= thresh) ? v[4*i+2] * scale : 0.f;
        o.w = (v[4*i+3] >= thresh) ? v[4*i+3] * scale : 0.f;
        orow[t + i * NTHREADS] = o;
    }
}

extern "C" void kernel_launch(void* const* d_in, const int* in_sizes, int n_in,
                              void* d_out, int out_size)
{
    const float* x = (const float*)d_in[0];
    float* out     = (float*)d_out;
    int rows = in_sizes[0] / D_COLS;     // 16384
    sparsify1d_kernel<<<rows, NTHREADS>>>(x, out);
}

// round 11
// speedup vs baseline: 1.0767x; 1.0767x over previous
#include <cuda_runtime.h>

#define D_COLS   4096
#define K_SEL    2048
#define NTHREADS 128
#define VPT      32               // D_COLS / NTHREADS
#define NWARP    (NTHREADS / 32)  // 4
#define CAND_MAX 32

#define F_PINF  __int_as_float(0x7f800000)
#define F_NINF  __int_as_float(0xff800000)
#define DENS0     1634.07f        // 4096 * phi(0)
#define INV_DENS0 6.119698e-4f    // 1 / DENS0
#define MARGIN    16.5f

// Monotone float <-> ordered-uint key mapping (total order matching float <)
__device__ __forceinline__ unsigned fkey(float f) {
    unsigned u = __float_as_uint(f);
    return u ^ ((u & 0x80000000u) ? 0xFFFFFFFFu : 0x80000000u);
}
__device__ __forceinline__ float funkey(unsigned k) {
    unsigned u = k ^ ((k & 0x80000000u) ? 0x80000000u : 0xFFFFFFFFu);
    return __uint_as_float(u);
}
__device__ __forceinline__ bool my_finite(float f) { return fabsf(f) < 3.0e38f; }

// block count of (v >= T). Mixed int/float accumulators to balance alu/fma pipes.
__device__ __forceinline__ int block_count(const float* v, float T,
                                           int4* s_slot, int lane, int wid)
{
    int   ci0 = 0, ci1 = 0;
    float cf0 = 0.f, cf1 = 0.f;
    #pragma unroll
    for (int i = 0; i < VPT; i += 4) {
        ci0 += (v[i+0] >= T);
        ci1 += (v[i+1] >= T);
        cf0 += (v[i+2] >= T) ? 1.f : 0.f;
        cf1 += (v[i+3] >= T) ? 1.f : 0.f;
    }
    int cc = (ci0 + ci1) + (int)(cf0 + cf1);
    cc = __reduce_add_sync(0xffffffffu, cc);
    if (lane == 0) ((int*)s_slot)[wid] = cc;
    __syncthreads();
    int4 p = *s_slot;
    return (p.x + p.y) + (p.z + p.w);
}

__global__ __launch_bounds__(NTHREADS, 8) void sparsify1d_kernel(
    const float* __restrict__ x, float* __restrict__ out)
{
    __shared__ __align__(16) int4  s_redi[2];
    __shared__ __align__(16) float s_redf[NWARP];
    __shared__ float s_thresh;
    __shared__ float s_csum;
    __shared__ int   s_ncand;
    __shared__ float s_cand[CAND_MAX];

    const int t    = threadIdx.x;
    const int lane = t & 31;
    const int wid  = t >> 5;
    const long long row = blockIdx.x;

    const float4* __restrict__ xr   = (const float4*)(x + row * (long long)D_COLS);
    float4* __restrict__       orow = (float4*)(out + row * (long long)D_COLS);

    if (t == 0) s_ncand = 0;      // published by probe A's reduction barrier

    // ---- load row into registers; FUSED probe A (count v >= 0) in load shadow ----
    float v[VPT];
    int   ca0 = 0, ca1 = 0;
    float ca2 = 0.f, ca3 = 0.f;
    #pragma unroll
    for (int i = 0; i < 8; i++) {
        float4 f4 = xr[t + i * NTHREADS];
        v[4*i+0] = f4.x; v[4*i+1] = f4.y; v[4*i+2] = f4.z; v[4*i+3] = f4.w;
        ca0 += (f4.x >= 0.f);
        ca1 += (f4.y >= 0.f);
        ca2 += (f4.z >= 0.f) ? 1.f : 0.f;
        ca3 += (f4.w >= 0.f) ? 1.f : 0.f;
    }
    int cA = (ca0 + ca1) + (int)(ca2 + ca3);
    cA = __reduce_add_sync(0xffffffffu, cA);
    if (lane == 0) ((int*)&s_redi[0])[wid] = cA;
    __syncthreads();
    {
        int4 p = s_redi[0];
        cA = (p.x + p.y) + (p.z + p.w);
    }

    // ---- probe B: Newton step from 0 ----
    float T1 = (float)(cA - K_SEL) * INV_DENS0;
    int   cB = block_count(v, T1, &s_redi[1], lane, wid);

    // ---- build bracket: count(>=lo)=clo >= K > chi=count(>=hi) ----
    float lo = F_NINF, hi = F_PINF;
    int clo = D_COLS, chi = 0;
    if (cA >= K_SEL) { lo = 0.0f; clo = cA; } else { hi = 0.0f; chi = cA; }
    if (T1 > lo && T1 < hi) {
        if (cB >= K_SEL) { lo = T1; clo = cB; } else { hi = T1; chi = cB; }
    }

    // ---- probe C: margin-targeted (aims count K -/+ MARGIN from nearer end) ----
    if (clo - chi > CAND_MAX) {
        float d_lo = (float)(clo - K_SEL);
        float d_hi = (float)(K_SEL - chi);
        bool fromLo = d_lo <= d_hi;
        float e  = fromLo ? lo : hi;
        float dd = fromLo ? d_lo : d_hi;
        float inv_dens = __expf(0.5f * e * e) * INV_DENS0;
        float step = (dd + MARGIN) * inv_dens;
        float T2 = fromLo ? (lo + step) : (hi - step);
        if (T2 > lo && T2 < hi) {
            int c2 = block_count(v, T2, &s_redi[0], lane, wid);
            if (c2 >= K_SEL) { lo = T2; clo = c2; }
            else             { hi = T2; chi = c2; }
        }
    }

    float thresh = 0.f;
    bool  have_thresh = false;
    int   par = 1;

    // ---- fallback refinement loop (rare) ----
    for (int iter = 0; iter < 48; iter++) {
        int m = clo - chi;
        if (m <= CAND_MAX) break;

        unsigned klo = fkey(lo), khi = fkey(hi);
        if (khi - klo <= 1u) { thresh = lo; have_thresh = true; break; }

        bool lof = my_finite(lo), hif = my_finite(hi);
        float stepl = (float)(clo - K_SEL) + 0.5f;
        float steph = (float)(K_SEL - chi) + 0.5f;
        float Ti = lo + (hi - lo) * (stepl / (float)m);
        float Tl = lo + stepl / (DENS0 * __expf(-0.5f * lo * lo));
        float Th = hi - steph / (DENS0 * __expf(-0.5f * hi * hi));
        float T  = (lof && hif) ? Ti : (lof ? Tl : Th);
        bool ok  = (T > lo) && (T < hi) && (iter < 12);
        if (!ok) T = funkey(klo + ((khi - klo) >> 1u));   // guaranteed progress

        int cc = block_count(v, T, &s_redi[par], lane, wid);
        par ^= 1;
        if (cc >= K_SEL) { lo = T; clo = cc; }
        else             { hi = T; chi = cc; }
    }

    float total;
    if (!have_thresh) {
        // ---- single sweep: predicated sum of v>=hi + warp-guarded gather ----
        float ssel = 0.f;
        #pragma unroll
        for (int i = 0; i < VPT; i++) {
            float f = v[i];
            ssel += (f >= hi) ? f : 0.f;
            bool inr = (f >= lo) && (f < hi);
            if (__any_sync(0xffffffffu, inr)) {     // warp-uniform skip
                if (inr) {
                    int idx = atomicAdd(&s_ncand, 1);
                    if (idx < CAND_MAX) s_cand[idx] = f;
                }
            }
        }
        ssel += __shfl_xor_sync(0xffffffffu, ssel, 16);
        ssel += __shfl_xor_sync(0xffffffffu, ssel, 8);
        ssel += __shfl_xor_sync(0xffffffffu, ssel, 4);
        ssel += __shfl_xor_sync(0xffffffffu, ssel, 2);
        ssel += __shfl_xor_sync(0xffffffffu, ssel, 1);
        if (lane == 0) s_redf[wid] = ssel;
        __syncthreads();
        float4 pf = *(const float4*)s_redf;
        float ssel_total = (pf.x + pf.y) + (pf.z + pf.w);

        // ---- warp 0: bitonic sort of <=32 candidates, pick j-th largest ----
        if (wid == 0) {
            int m2 = s_ncand;             // == clo - chi  (<= 32)
            int j  = K_SEL - chi;         // 1-indexed descending rank
            float val = (lane < m2) ? s_cand[lane] : F_NINF;
            #pragma unroll
            for (int k = 2; k <= 32; k <<= 1) {
                #pragma unroll
                for (int jj = k >> 1; jj > 0; jj >>= 1) {
                    float other = __shfl_xor_sync(0xffffffffu, val, jj);
                    bool up    = ((lane & k)  == 0);
                    bool lower = ((lane & jj) == 0);
                    float mn = fminf(val, other), mx = fmaxf(val, other);
                    val = (up == lower) ? mn : mx;   // ascending sort
                }
            }
            float th = __shfl_sync(0xffffffffu, val, 32 - j);  // j-th largest
            float cs = (val >= th) ? val : 0.f;    // -inf padding excluded
            cs += __shfl_xor_sync(0xffffffffu, cs, 16);
            cs += __shfl_xor_sync(0xffffffffu, cs, 8);
            cs += __shfl_xor_sync(0xffffffffu, cs, 4);
            cs += __shfl_xor_sync(0xffffffffu, cs, 2);
            cs += __shfl_xor_sync(0xffffffffu, cs, 1);
            if (lane == 0) { s_thresh = th; s_csum = cs; }
        }
        __syncthreads();
        thresh = s_thresh;
        total  = ssel_total + s_csum;
    } else {
        // ---- rare path: thresh known exactly; plain masked sum ----
        float ss = 0.f;
        #pragma unroll
        for (int i = 0; i < VPT; i++) ss += (v[i] >= thresh) ? v[i] : 0.f;
        ss += __shfl_xor_sync(0xffffffffu, ss, 16);
        ss += __shfl_xor_sync(0xffffffffu, ss, 8);
        ss += __shfl_xor_sync(0xffffffffu, ss, 4);
        ss += __shfl_xor_sync(0xffffffffu, ss, 2);
        ss += __shfl_xor_sync(0xffffffffu, ss, 1);
        if (lane == 0) s_redf[wid] = ss;
        __syncthreads();
        float4 pf = *(const float4*)s_redf;
        total = (pf.x + pf.y) + (pf.z + pf.w);
    }

    float scale = (float)D_COLS / total;   // out = res * D / sum(res)

    // ---- final predicated scale + coalesced store ----
    #pragma unroll
    for (int i = 0; i < 8; i++) {
        float4 o;
        o.x = (v[4*i+0] >= thresh) ? v[4*i+0] * scale : 0.f;
        o.y = (v[4*i+1] >= thresh) ? v[4*i+1] * scale : 0.f;
        o.z = (v[4*i+2] >= thresh) ? v[4*i+2] * scale : 0.f;
        o.w = (v[4*i+3] >= thresh) ? v[4*i+3] * scale : 0.f;
        orow[t + i * NTHREADS] = o;
    }
}

extern "C" void kernel_launch(void* const* d_in, const int* in_sizes, int n_in,
                              void* d_out, int out_size)
{
    const float* x = (const float*)d_in[0];
    float* out     = (float*)d_out;
    int rows = in_sizes[0] / D_COLS;     // 16384
    sparsify1d_kernel<<<rows, NTHREADS>>>(x, out);
}